// round 4
// baseline (speedup 1.0000x reference)
#include <cuda_runtime.h>
#include <stdint.h>
#include <stddef.h>

#define N0   32768
#define NP1  2048
#define NS1  32
#define NP2  512
#define NS2  64

// ---------------- static scratch (no runtime allocation allowed) ----------------
__device__ float4 g_xyz[N0];
__device__ float  g_feats[N0 * 12];
__device__ int    g_idx1[NP1];
__device__ float4 g_newxyz1[NP1];
__device__ int    g_gidx1[NP1 * NS1];
__device__ float  g_h0[NP1 * NS1 * 16];            // SA1 L0 input, K 15->16
__device__ float  g_bufA[65536 * 64];              // 16 MB
__device__ float  g_bufB[65536 * 64];              // 16 MB
__device__ float  g_bufC[65536 * 128];             // 32 MB
__device__ float  g_bufD[32768 * 256];             // 32 MB
__device__ float  g_f1[NP1 * 128];
__device__ int    g_idx2[NP2];
__device__ float4 g_newxyz2[NP2];
__device__ int    g_gidx2[NP2 * NS2];
__device__ float  g_f2[NP2 * 256];
__device__ float  g_a3[NP2 * 272];                 // SA3 input, K 259->272
__device__ float  g_wp[64*16 + 128*144 + 256*272]; // padded weights
__device__ uint4  g_partials[16];
__device__ uint4  g_release;

#define WP1_OFF 0
#define WP2_OFF (64*16)
#define WP3_OFF (64*16 + 128*144)

// ---------------- helpers ----------------
__device__ __forceinline__ uint4 ldv4(const uint4* p) {
    uint4 v;
    asm volatile("ld.volatile.global.v4.u32 {%0,%1,%2,%3}, [%4];"
                 : "=r"(v.x), "=r"(v.y), "=r"(v.z), "=r"(v.w) : "l"(p));
    return v;
}
__device__ __forceinline__ void stv4(uint4* p, uint4 v) {
    asm volatile("st.volatile.global.v4.u32 [%0], {%1,%2,%3,%4};"
                 :: "l"(p), "r"(v.x), "r"(v.y), "r"(v.z), "r"(v.w) : "memory");
}
// square-then-add (no FMA) to mirror XLA's elementwise (x-c)**2 then reduce
__device__ __forceinline__ float sqdist(float px, float py, float pz,
                                        float cx, float cy, float cz) {
    float dx = __fsub_rn(px, cx), dy = __fsub_rn(py, cy), dz = __fsub_rn(pz, cz);
    return __fadd_rn(__fadd_rn(__fmul_rn(dx, dx), __fmul_rn(dy, dy)), __fmul_rn(dz, dz));
}

// ---------------- stage 0: xyz + feats ----------------
__global__ void prep_kernel(const float* __restrict__ pts, const float* __restrict__ prop) {
    int i = blockIdx.x * blockDim.x + threadIdx.x;
    if (i >= N0) return;
    float x = prop[0], y = prop[1], w = prop[3];
    float hw = __fmul_rn(w, 0.5f);
    float px = pts[i * 3 + 0], py = pts[i * 3 + 1], pz = pts[i * 3 + 2];
    float ax = __fsub_rn(px, x), ay = __fsub_rn(py, y);
    g_xyz[i] = make_float4(ax, ay, pz, 0.f);
    float oxp = __fadd_rn(x, hw), oxm = __fsub_rn(x, hw);
    float oyp = __fadd_rn(y, hw), oym = __fsub_rn(y, hw);
    float* f = &g_feats[(size_t)i * 12];
    f[0] = __fsub_rn(px, oxp); f[1]  = ay;                 f[2]  = pz;
    f[3] = __fsub_rn(px, oxm); f[4]  = ay;                 f[5]  = pz;
    f[6] = ax;                 f[7]  = __fsub_rn(py, oyp); f[8]  = pz;
    f[9] = ax;                 f[10] = __fsub_rn(py, oym); f[11] = pz;
}

// ---------------- FPS1: 16 persistent blocks, tagged L2 spin protocol -------
__global__ void __launch_bounds__(512) fps1_kernel(int* __restrict__ idx_out) {
    __shared__ float sval[16];
    __shared__ int   sidx[16];
    const int b = blockIdx.x, t = threadIdx.x;
    const int lane = t & 31, wp = t >> 5;
    const int base = b * 2048;
    float px[4], py[4], pz[4], dst[4];
#pragma unroll
    for (int j = 0; j < 4; j++) {
        float4 p = g_xyz[base + j * 512 + t];
        px[j] = p.x; py[j] = p.y; pz[j] = p.z; dst[j] = 1e10f;
    }
    int cur = 0;
    float ccx = 0.f, ccy = 0.f, ccz = 0.f;
    if (b == 0 && t == 0) { float4 c = g_xyz[0]; ccx = c.x; ccy = c.y; ccz = c.z; }

    for (int i = 0; i < NP1; i++) {
        const unsigned tag = (unsigned)(i + 1);
        if (b == 0 && t == 0) {
            idx_out[i] = cur;
            stv4(&g_release, make_uint4(tag, __float_as_uint(ccx),
                                        __float_as_uint(ccy), __float_as_uint(ccz)));
        }
        uint4 r;
        if (lane == 0) { do { r = ldv4(&g_release); } while (r.x != tag); }
        r.y = __shfl_sync(0xffffffffu, r.y, 0);
        r.z = __shfl_sync(0xffffffffu, r.z, 0);
        r.w = __shfl_sync(0xffffffffu, r.w, 0);
        float cx = __uint_as_float(r.y), cy = __uint_as_float(r.z), cz = __uint_as_float(r.w);

        float bv = -1.f; int bi = 0x7fffffff;
#pragma unroll
        for (int j = 0; j < 4; j++) {
            float d = sqdist(px[j], py[j], pz[j], cx, cy, cz);
            dst[j] = fminf(dst[j], d);
            if (dst[j] > bv) { bv = dst[j]; bi = base + j * 512 + t; }
        }
#pragma unroll
        for (int o = 16; o; o >>= 1) {
            float ov = __shfl_down_sync(0xffffffffu, bv, o);
            int   oi = __shfl_down_sync(0xffffffffu, bi, o);
            if (ov > bv || (ov == bv && oi < bi)) { bv = ov; bi = oi; }
        }
        if (lane == 0) { sval[wp] = bv; sidx[wp] = bi; }
        __syncthreads();
        if (wp == 0) {
            float v  = (lane < 16) ? sval[lane] : -1.f;
            int   id = (lane < 16) ? sidx[lane] : 0x7fffffff;
#pragma unroll
            for (int o = 8; o; o >>= 1) {
                float ov = __shfl_down_sync(0xffffffffu, v, o);
                int   oi = __shfl_down_sync(0xffffffffu, id, o);
                if (ov > v || (ov == v && oi < id)) { v = ov; id = oi; }
            }
            if (lane == 0)
                stv4(&g_partials[b], make_uint4(tag, __float_as_uint(v), (unsigned)id, 0u));
        }
        if (b == 0 && wp == 0) {
            float v; int id;
            if (lane < 16) {
                uint4 p;
                do { p = ldv4(&g_partials[lane]); } while (p.x != tag);
                v = __uint_as_float(p.y); id = (int)p.z;
            } else { v = -1.f; id = 0x7fffffff; }
#pragma unroll
            for (int o = 8; o; o >>= 1) {
                float ov = __shfl_down_sync(0xffffffffu, v, o);
                int   oi = __shfl_down_sync(0xffffffffu, id, o);
                if (ov > v || (ov == v && oi < id)) { v = ov; id = oi; }
            }
            if (lane == 0) { cur = id; float4 c = g_xyz[cur]; ccx = c.x; ccy = c.y; ccz = c.z; }
        }
    }
}

// ---------------- FPS2: single block, all in smem ----------------
__global__ void __launch_bounds__(512) fps2_kernel(int* __restrict__ idx_out) {
    __shared__ float4 sx[NP1];
    __shared__ float  sval[16];
    __shared__ int    sidx[16];
    __shared__ float4 scent;
    const int t = threadIdx.x, lane = t & 31, wp = t >> 5;
    for (int i = t; i < NP1; i += 512) sx[i] = g_newxyz1[i];
    __syncthreads();
    float px[4], py[4], pz[4], dst[4];
#pragma unroll
    for (int j = 0; j < 4; j++) {
        float4 p = sx[j * 512 + t];
        px[j] = p.x; py[j] = p.y; pz[j] = p.z; dst[j] = 1e10f;
    }
    int cur = 0;
    for (int i = 0; i < NP2; i++) {
        if (t == 0) { idx_out[i] = cur; scent = sx[cur]; }
        __syncthreads();
        float cx = scent.x, cy = scent.y, cz = scent.z;
        float bv = -1.f; int bi = 0x7fffffff;
#pragma unroll
        for (int j = 0; j < 4; j++) {
            float d = sqdist(px[j], py[j], pz[j], cx, cy, cz);
            dst[j] = fminf(dst[j], d);
            if (dst[j] > bv) { bv = dst[j]; bi = j * 512 + t; }
        }
#pragma unroll
        for (int o = 16; o; o >>= 1) {
            float ov = __shfl_down_sync(0xffffffffu, bv, o);
            int   oi = __shfl_down_sync(0xffffffffu, bi, o);
            if (ov > bv || (ov == bv && oi < bi)) { bv = ov; bi = oi; }
        }
        if (lane == 0) { sval[wp] = bv; sidx[wp] = bi; }
        __syncthreads();
        if (wp == 0) {
            float v  = (lane < 16) ? sval[lane] : -1.f;
            int   id = (lane < 16) ? sidx[lane] : 0x7fffffff;
#pragma unroll
            for (int o = 8; o; o >>= 1) {
                float ov = __shfl_down_sync(0xffffffffu, v, o);
                int   oi = __shfl_down_sync(0xffffffffu, id, o);
                if (ov > v || (ov == v && oi < id)) { v = ov; id = oi; }
            }
            if (lane == 0) cur = id;
        }
    }
}

// ---------------- gather ----------------
__global__ void gather_kernel(const float4* __restrict__ src, const int* __restrict__ idx,
                              float4* __restrict__ dst, int n) {
    int i = blockIdx.x * blockDim.x + threadIdx.x;
    if (i < n) dst[i] = src[idx[i]];
}

// ------ ball query: warp/center ascending scan == top_k of smallest indices ------
__global__ void ballquery_kernel(const float4* __restrict__ pts, int n,
                                 const float4* __restrict__ centers, int rows,
                                 float r2, int nsample, int* __restrict__ gidx) {
    int gw = (blockIdx.x * blockDim.x + threadIdx.x) >> 5;
    int lane = threadIdx.x & 31;
    if (gw >= rows) return;
    float4 c = centers[gw];
    int found = 0, first = 0;
    int* out = &gidx[(size_t)gw * nsample];
    for (int base = 0; base < n; base += 32) {
        int j = base + lane;
        float4 p = pts[j];
        float d = sqdist(p.x, p.y, p.z, c.x, c.y, c.z);
        bool in = (d <= r2);
        unsigned m = __ballot_sync(0xffffffffu, in);
        if (found == 0 && m) first = base + __ffs(m) - 1;
        int pos = found + __popc(m & ((1u << lane) - 1u));
        if (in && pos < nsample) out[pos] = j;
        found += __popc(m);
        if (found >= nsample) break;
    }
    for (int p = found + lane; p < nsample; p += 32) out[p] = first;
}

// ---------------- grouping ----------------
__global__ void group1_kernel() {
    int m = blockIdx.x * blockDim.x + threadIdx.x;   // < 65536
    int s = m >> 5;
    int g = g_gidx1[m];
    float4 p = g_xyz[g], c = g_newxyz1[s];
    float* o = &g_h0[(size_t)m * 16];
    o[0] = __fsub_rn(p.x, c.x); o[1] = __fsub_rn(p.y, c.y); o[2] = __fsub_rn(p.z, c.z);
    const float* f = &g_feats[(size_t)g * 12];
#pragma unroll
    for (int j = 0; j < 12; j++) o[3 + j] = f[j];
    o[15] = 0.f;
}

__global__ void group2_kernel() {
    int m = blockIdx.x * blockDim.x + threadIdx.x;   // < 32768
    int s = m >> 6;
    int g = g_gidx2[m];
    float4 p = g_newxyz1[g], c = g_newxyz2[s];
    float* o = &g_bufC[(size_t)m * 144];
    o[0] = __fsub_rn(p.x, c.x); o[1] = __fsub_rn(p.y, c.y); o[2] = __fsub_rn(p.z, c.z);
    const float* f = &g_f1[(size_t)g * 128];
#pragma unroll 4
    for (int j = 0; j < 128; j++) o[3 + j] = f[j];
#pragma unroll
    for (int j = 131; j < 144; j++) o[j] = 0.f;
}

__global__ void a3_kernel() {
    int i = blockIdx.x * blockDim.x + threadIdx.x;
    if (i >= NP2 * 272) return;
    int s = i / 272, c = i % 272;
    float v;
    if (c < 3)        { float4 p = g_newxyz2[s]; v = (c == 0) ? p.x : ((c == 1) ? p.y : p.z); }
    else if (c < 259)   v = g_f2[(size_t)s * 256 + (c - 3)];
    else                v = 0.f;
    g_a3[i] = v;
}

// ---------------- weight padding ----------------
__global__ void padw_kernel(const float* __restrict__ W, float* __restrict__ WP,
                            int O, int K, int KP) {
    int i = blockIdx.x * blockDim.x + threadIdx.x;
    if (i >= O * KP) return;
    int o = i / KP, k = i % KP;
    WP[i] = (k < K) ? W[(size_t)o * K + k] : 0.f;
}

// -------- SGEMM: C[M,N] = relu(A[M,K] * W[N,K]^T + bias), M%128==0, N%64==0, K%16==0
__global__ void __launch_bounds__(256) gemm_bias_relu(
    const float* __restrict__ A, const float* __restrict__ W,
    const float* __restrict__ bias, float* __restrict__ C,
    int M, int N, int K)
{
    __shared__ float As[16][132];
    __shared__ float Bs[16][68];
    const int m0 = blockIdx.x * 128;
    const int n0 = blockIdx.y * 64;
    const int tid = threadIdx.x;
    const int tx = tid & 15, ty = tid >> 4;
    float acc[8][4];
#pragma unroll
    for (int i = 0; i < 8; i++)
#pragma unroll
        for (int j = 0; j < 4; j++) acc[i][j] = 0.f;

    for (int k0 = 0; k0 < K; k0 += 16) {
#pragma unroll
        for (int t = 0; t < 2; t++) {
            int idx = tid + t * 256;
            int row = idx >> 2, c4 = (idx & 3) << 2;
            float4 v = *reinterpret_cast<const float4*>(A + (size_t)(m0 + row) * K + k0 + c4);
            As[c4][row] = v.x; As[c4 + 1][row] = v.y; As[c4 + 2][row] = v.z; As[c4 + 3][row] = v.w;
        }
        {
            int row = tid >> 2, c4 = (tid & 3) << 2;
            float4 v = *reinterpret_cast<const float4*>(W + (size_t)(n0 + row) * K + k0 + c4);
            Bs[c4][row] = v.x; Bs[c4 + 1][row] = v.y; Bs[c4 + 2][row] = v.z; Bs[c4 + 3][row] = v.w;
        }
        __syncthreads();
#pragma unroll
        for (int k = 0; k < 16; k++) {
            float a[8], bb[4];
            *reinterpret_cast<float4*>(&a[0]) = *reinterpret_cast<const float4*>(&As[k][ty * 8]);
            *reinterpret_cast<float4*>(&a[4]) = *reinterpret_cast<const float4*>(&As[k][ty * 8 + 4]);
            *reinterpret_cast<float4*>(&bb[0]) = *reinterpret_cast<const float4*>(&Bs[k][tx * 4]);
#pragma unroll
            for (int i = 0; i < 8; i++)
#pragma unroll
                for (int j = 0; j < 4; j++)
                    acc[i][j] += a[i] * bb[j];
        }
        __syncthreads();
    }
    float4 bv = *reinterpret_cast<const float4*>(bias + n0 + tx * 4);
#pragma unroll
    for (int i = 0; i < 8; i++) {
        float4 o;
        o.x = fmaxf(acc[i][0] + bv.x, 0.f);
        o.y = fmaxf(acc[i][1] + bv.y, 0.f);
        o.z = fmaxf(acc[i][2] + bv.z, 0.f);
        o.w = fmaxf(acc[i][3] + bv.w, 0.f);
        *reinterpret_cast<float4*>(C + (size_t)(m0 + ty * 8 + i) * N + n0 + tx * 4) = o;
    }
}

// ---------------- max pools ----------------
__global__ void maxpool1_kernel() {
    int i = blockIdx.x * blockDim.x + threadIdx.x;   // < 2048*128
    int s = i >> 7, c = i & 127;
    const float* base = &g_bufC[(size_t)s * 32 * 128 + c];
    float v = base[0];
#pragma unroll
    for (int k = 1; k < 32; k++) v = fmaxf(v, base[(size_t)k * 128]);
    g_f1[i] = v;
}
__global__ void maxpool2_kernel() {
    int i = blockIdx.x * blockDim.x + threadIdx.x;   // < 512*256
    int s = i >> 8, c = i & 255;
    const float* base = &g_bufD[(size_t)s * 64 * 256 + c];
    float v = base[0];
#pragma unroll
    for (int k = 1; k < 64; k++) v = fmaxf(v, base[(size_t)k * 256]);
    g_f2[i] = v;
}
__global__ void finalmax_kernel(float* __restrict__ out) {
    int c = blockIdx.x * blockDim.x + threadIdx.x;
    if (c >= 1024) return;
    float v = g_bufC[c];
    for (int s = 1; s < 512; s++) v = fmaxf(v, g_bufC[(size_t)s * 1024 + c]);
    out[c] = v;
}

// ---------------- launch ----------------
extern "C" void kernel_launch(void* const* d_in, const int* in_sizes, int n_in,
                              void* d_out, int out_size) {
    const float* points = (const float*)d_in[0];
    const float* prop   = (const float*)d_in[1];

    // Input binding: runtime-detect tensor ordering.
    //   signature order: w0,w1,w2,b0,b1,b2 per SA  -> in_sizes[3] = 64*64 = 4096
    //   dict order:      w0,b0,w1,b1,w2,b2 per SA  -> in_sizes[3] = 64
    const float *w10, *w11, *w12, *b10, *b11, *b12;
    const float *w20, *w21, *w22, *b20, *b21, *b22;
    const float *w30, *w31, *w32, *b30, *b31, *b32;
    if (in_sizes[3] == 64) {
        // interleaved (dict) order: w0,b0,w1,b1,w2,b2
        w10 = (const float*)d_in[2];  b10 = (const float*)d_in[3];
        w11 = (const float*)d_in[4];  b11 = (const float*)d_in[5];
        w12 = (const float*)d_in[6];  b12 = (const float*)d_in[7];
        w20 = (const float*)d_in[8];  b20 = (const float*)d_in[9];
        w21 = (const float*)d_in[10]; b21 = (const float*)d_in[11];
        w22 = (const float*)d_in[12]; b22 = (const float*)d_in[13];
        w30 = (const float*)d_in[14]; b30 = (const float*)d_in[15];
        w31 = (const float*)d_in[16]; b31 = (const float*)d_in[17];
        w32 = (const float*)d_in[18]; b32 = (const float*)d_in[19];
    } else {
        // signature order: w0,w1,w2,b0,b1,b2
        w10 = (const float*)d_in[2];  w11 = (const float*)d_in[3];  w12 = (const float*)d_in[4];
        b10 = (const float*)d_in[5];  b11 = (const float*)d_in[6];  b12 = (const float*)d_in[7];
        w20 = (const float*)d_in[8];  w21 = (const float*)d_in[9];  w22 = (const float*)d_in[10];
        b20 = (const float*)d_in[11]; b21 = (const float*)d_in[12]; b22 = (const float*)d_in[13];
        w30 = (const float*)d_in[14]; w31 = (const float*)d_in[15]; w32 = (const float*)d_in[16];
        b30 = (const float*)d_in[17]; b31 = (const float*)d_in[18]; b32 = (const float*)d_in[19];
    }
    float* out = (float*)d_out;

    float *h0, *bufA, *bufB, *bufC, *bufD, *wp, *a3;
    float4 *xyz, *nx1, *nx2;
    int *idx1, *idx2, *gidx1, *gidx2;
    cudaGetSymbolAddress((void**)&h0,    g_h0);
    cudaGetSymbolAddress((void**)&bufA,  g_bufA);
    cudaGetSymbolAddress((void**)&bufB,  g_bufB);
    cudaGetSymbolAddress((void**)&bufC,  g_bufC);
    cudaGetSymbolAddress((void**)&bufD,  g_bufD);
    cudaGetSymbolAddress((void**)&wp,    g_wp);
    cudaGetSymbolAddress((void**)&a3,    g_a3);
    cudaGetSymbolAddress((void**)&xyz,   g_xyz);
    cudaGetSymbolAddress((void**)&nx1,   g_newxyz1);
    cudaGetSymbolAddress((void**)&nx2,   g_newxyz2);
    cudaGetSymbolAddress((void**)&idx1,  g_idx1);
    cudaGetSymbolAddress((void**)&idx2,  g_idx2);
    cudaGetSymbolAddress((void**)&gidx1, g_gidx1);
    cudaGetSymbolAddress((void**)&gidx2, g_gidx2);

    const float r2_1 = (float)(0.4 * 0.4);
    const float r2_2 = (float)(0.8 * 0.8);

    // stage 0
    prep_kernel<<<N0 / 256, 256>>>(points, prop);
    // weight padding (independent, do early)
    padw_kernel<<<(64 * 16 + 255) / 256, 256>>>(w10, wp + WP1_OFF, 64, 15, 16);
    padw_kernel<<<(128 * 144 + 255) / 256, 256>>>(w20, wp + WP2_OFF, 128, 131, 144);
    padw_kernel<<<(256 * 272 + 255) / 256, 256>>>(w30, wp + WP3_OFF, 256, 259, 272);

    // SA1
    fps1_kernel<<<16, 512>>>(idx1);
    gather_kernel<<<(NP1 + 255) / 256, 256>>>(xyz, idx1, nx1, NP1);
    ballquery_kernel<<<(NP1 * 32 + 255) / 256, 256>>>(xyz, N0, nx1, NP1, r2_1, NS1, gidx1);
    group1_kernel<<<(NP1 * NS1 + 255) / 256, 256>>>();
    {
        dim3 g1(65536 / 128, 1);  gemm_bias_relu<<<g1, 256>>>(h0,   wp + WP1_OFF, b10, bufA, 65536, 64, 16);
        dim3 g2(65536 / 128, 1);  gemm_bias_relu<<<g2, 256>>>(bufA, w11,          b11, bufB, 65536, 64, 64);
        dim3 g3(65536 / 128, 2);  gemm_bias_relu<<<g3, 256>>>(bufB, w12,          b12, bufC, 65536, 128, 64);
    }
    maxpool1_kernel<<<(NP1 * 128 + 255) / 256, 256>>>();

    // SA2
    fps2_kernel<<<1, 512>>>(idx2);
    gather_kernel<<<(NP2 + 255) / 256, 256>>>(nx1, idx2, nx2, NP2);
    ballquery_kernel<<<(NP2 * 32 + 255) / 256, 256>>>(nx1, NP1, nx2, NP2, r2_2, NS2, gidx2);
    group2_kernel<<<(NP2 * NS2 + 255) / 256, 256>>>();
    {
        dim3 g4(32768 / 128, 2);  gemm_bias_relu<<<g4, 256>>>(bufC, wp + WP2_OFF, b20, bufA, 32768, 128, 144);
        dim3 g5(32768 / 128, 2);  gemm_bias_relu<<<g5, 256>>>(bufA, w21,          b21, bufB, 32768, 128, 128);
        dim3 g6(32768 / 128, 4);  gemm_bias_relu<<<g6, 256>>>(bufB, w22,          b22, bufD, 32768, 256, 128);
    }
    maxpool2_kernel<<<(NP2 * 256 + 255) / 256, 256>>>();

    // SA3
    a3_kernel<<<(NP2 * 272 + 255) / 256, 256>>>();
    {
        dim3 g7(512 / 128, 4);    gemm_bias_relu<<<g7, 256>>>(a3,   wp + WP3_OFF, b30, bufA, 512, 256, 272);
        dim3 g8(512 / 128, 8);    gemm_bias_relu<<<g8, 256>>>(bufA, w31,          b31, bufB, 512, 512, 256);
        dim3 g9(512 / 128, 16);   gemm_bias_relu<<<g9, 256>>>(bufB, w32,          b32, bufC, 512, 1024, 512);
    }
    finalmax_kernel<<<4, 256>>>(out);
}